// round 6
// baseline (speedup 1.0000x reference)
#include <cuda_runtime.h>
#include <cstdint>

#define BB 16
#define NN 2048
#define HH 128
#define KNN 16

// ---------------- scratch (device globals; no allocs allowed) ----------------
__device__ int   g_nbr[BB * NN * KNN];      // local (per-batch) neighbor indices
__device__ float g_h1[BB * NN * HH];
__device__ float g_h2[BB * NN * HH];
__device__ float g_WT[4 * HH * HH];         // W2r^T, W2s^T, W3r^T, W3s^T (k-major)

// ---------------- kNN: brute force, smem-resident candidates ----------------
// grid (16 slices, 16 batches), block 128. One thread = one query point.
__global__ __launch_bounds__(128) void knn_kernel(const float* __restrict__ pts) {
    __shared__ float4 sp[NN];   // (x, y, z, |p|^2) : 32KB
    const int b = blockIdx.y;
    const float* pb = pts + (size_t)b * NN * 3;
    for (int j = threadIdx.x; j < NN; j += 128) {
        float x = pb[j * 3], y = pb[j * 3 + 1], z = pb[j * 3 + 2];
        sp[j] = make_float4(x, y, z, x * x + y * y + z * z);
    }
    __syncthreads();

    const int i = blockIdx.x * 128 + threadIdx.x;
    const float4 p = sp[i];

    float bd[KNN];
    int   bi[KNN];
#pragma unroll
    for (int s = 0; s < KNN; s++) { bd[s] = 3.4e38f; bi[s] = 0; }
    float wv = 3.4e38f;   // current worst (max) of the kept set

    for (int j = 0; j < NN; j++) {
        float4 q = sp[j];
        float dot = p.x * q.x + p.y * q.y + p.z * q.z;
        float d2 = p.w + q.w - 2.0f * dot;   // same formula as the reference
        if (d2 < wv) {
            bool done = false;
#pragma unroll
            for (int s = 0; s < KNN; s++) {
                if (!done && bd[s] == wv) { bd[s] = d2; bi[s] = j; done = true; }
            }
            wv = bd[0];
#pragma unroll
            for (int s = 1; s < KNN; s++) wv = fmaxf(wv, bd[s]);
        }
    }

    int* o = g_nbr + ((size_t)b * NN + i) * KNN;
#pragma unroll
    for (int s = 0; s < KNN; s++) o[s] = bi[s];
}

// ---------------- layer 1 (input dim 3): 1 thread per point ------------------
// grid 128, block 256.
__global__ __launch_bounds__(256) void layer1_kernel(const float* __restrict__ pts,
                                                     const float* __restrict__ W1r,
                                                     const float* __restrict__ b1,
                                                     const float* __restrict__ W1s) {
    __shared__ float sWr[HH * 3], sWs[HH * 3], sb[HH];
    const int tid = threadIdx.x;
    // FIX (R6): block has 256 threads; 384 elements need a strided loop.
    for (int t = tid; t < HH * 3; t += 256) { sWr[t] = W1r[t]; sWs[t] = W1s[t]; }
    if (tid < 128) sb[tid] = b1[tid];
    __syncthreads();

    const int i = blockIdx.x * 256 + tid;     // global point index
    const int base = (i >> 11) << 11;         // batch base (N = 2048)

    const float* xp = pts + (size_t)i * 3;
    const float x0 = xp[0], x1 = xp[1], x2 = xp[2];

    float a0 = 0.f, a1 = 0.f, a2 = 0.f;
    const int* nb = g_nbr + (size_t)i * KNN;
#pragma unroll
    for (int n = 0; n < KNN; n++) {
        int j = nb[n];
        const float* c = pts + (size_t)(base + j) * 3;
        a0 += c[0]; a1 += c[1]; a2 += c[2];
    }

    float* orow = g_h1 + (size_t)i * HH;
#pragma unroll 2
    for (int h = 0; h < HH; h += 4) {
        float4 v;
        float* vv = (float*)&v;
#pragma unroll
        for (int e = 0; e < 4; e++) {
            int hh = h + e;
            float s = sb[hh]
                    + sWr[hh * 3 + 0] * a0 + sWr[hh * 3 + 1] * a1 + sWr[hh * 3 + 2] * a2
                    + sWs[hh * 3 + 0] * x0 + sWs[hh * 3 + 1] * x1 + sWs[hh * 3 + 2] * x2;
            vv[e] = fmaxf(s, 0.0f);
        }
        *(float4*)(orow + h) = v;
    }
}

// ---------------- W transpose (k-major for coalesced GEMM staging) -----------
// grid (64, 4), block 256
__global__ __launch_bounds__(256) void transpose_kernel(const float* __restrict__ W2r,
                                                        const float* __restrict__ W2s,
                                                        const float* __restrict__ W3r,
                                                        const float* __restrict__ W3s) {
    const float* src[4] = {W2r, W2s, W3r, W3s};
    int m = blockIdx.y;
    int idx = blockIdx.x * 256 + threadIdx.x;   // 0..16383
    int k = idx >> 7, h = idx & 127;
    g_WT[m * HH * HH + k * HH + h] = src[m][h * HH + k];
}

// ---------------- layers 2/3: gather + dual GEMM (scalar FFMA) ---------------
// grid 512, block 256, 64 points per block. dyn smem 83968 B.
#define APITCH 132

template <bool RELU>
__global__ __launch_bounds__(256) void layer_kernel(const float* __restrict__ xin,
                                                    const float* __restrict__ WrT,
                                                    const float* __restrict__ bvec,
                                                    const float* __restrict__ WsT,
                                                    float* __restrict__ xout) {
    extern __shared__ float smf[];
    float* As   = smf;                       // [64][APITCH] neighbor-sum
    float* Xs   = smf + 64 * APITCH;         // [64][APITCH] self features
    float* Wr_s = smf + 2 * 64 * APITCH;     // [16][128]
    float* Ws_s = Wr_s + 16 * HH;            // [16][128]

    const int tid = threadIdx.x;
    const int P0 = blockIdx.x * 64;
    const int base = (P0 >> 11) << 11;

    // ---- gather phase: 4 threads per point, each owns 32 dims ----
    {
        const int p = tid >> 2, c = tid & 3;
        const float4* xr = (const float4*)(xin + ((size_t)P0 + p) * HH + c * 32);
        float4 acc[8];
#pragma unroll
        for (int q = 0; q < 8; q++) {
            float4 v = xr[q];
            *(float4*)(Xs + p * APITCH + c * 32 + q * 4) = v;
            acc[q] = make_float4(0.f, 0.f, 0.f, 0.f);
        }
        const int* nb = g_nbr + ((size_t)P0 + p) * KNN;
        for (int n = 0; n < KNN; n++) {
            int j = nb[n];
            const float4* ar = (const float4*)(xin + ((size_t)base + j) * HH + c * 32);
#pragma unroll
            for (int q = 0; q < 8; q++) {
                float4 v = ar[q];
                acc[q].x += v.x; acc[q].y += v.y; acc[q].z += v.z; acc[q].w += v.w;
            }
        }
#pragma unroll
        for (int q = 0; q < 8; q++)
            *(float4*)(As + p * APITCH + c * 32 + q * 4) = acc[q];
    }

    // ---- GEMM phase: warp owns 8 rows (m), lane owns 4 cols (h) ----
    const int warp = tid >> 5, lane = tid & 31;
    const int m0 = warp * 8, h0 = lane * 4;

    float acc[8][4];
#pragma unroll
    for (int i = 0; i < 8; i++)
#pragma unroll
        for (int j = 0; j < 4; j++) acc[i][j] = 0.f;

    for (int k0 = 0; k0 < HH; k0 += 16) {
        __syncthreads();   // also covers gather -> first compute
        {
            const float4* s1 = (const float4*)(WrT + (size_t)k0 * HH);
            const float4* s2 = (const float4*)(WsT + (size_t)k0 * HH);
            ((float4*)Wr_s)[tid] = s1[tid]; ((float4*)Wr_s)[tid + 256] = s1[tid + 256];
            ((float4*)Ws_s)[tid] = s2[tid]; ((float4*)Ws_s)[tid + 256] = s2[tid + 256];
        }
        __syncthreads();
#pragma unroll
        for (int kk = 0; kk < 16; kk++) {
            const int k = k0 + kk;
            float a[8], x[8];
#pragma unroll
            for (int i = 0; i < 8; i++) {
                a[i] = As[(m0 + i) * APITCH + k];   // broadcast across lanes
                x[i] = Xs[(m0 + i) * APITCH + k];
            }
            float4 wr = *(const float4*)(Wr_s + kk * HH + h0);
            float4 ws = *(const float4*)(Ws_s + kk * HH + h0);
            const float* wrf = (const float*)&wr;
            const float* wsf = (const float*)&ws;
#pragma unroll
            for (int i = 0; i < 8; i++)
#pragma unroll
                for (int j = 0; j < 4; j++)
                    acc[i][j] += a[i] * wrf[j] + x[i] * wsf[j];
        }
    }

    // ---- epilogue: + bias, optional relu, vectorized row stores ----
    const float4 bv = *(const float4*)(bvec + h0);
    const float* bf = (const float*)&bv;
#pragma unroll
    for (int i = 0; i < 8; i++) {
        float4 o; float* of = (float*)&o;
#pragma unroll
        for (int j = 0; j < 4; j++) {
            float v = acc[i][j] + bf[j];
            if (RELU) v = fmaxf(v, 0.0f);
            of[j] = v;
        }
        *(float4*)(xout + ((size_t)P0 + m0 + i) * HH + h0) = o;
    }
}

// ---------------- launch: bind inputs BY SIZE (order-robust) ----------------
extern "C" void kernel_launch(void* const* d_in, const int* in_sizes, int n_in,
                              void* d_out, int out_size) {
    const float* pts = nullptr;
    const float* w3[2]  = {nullptr, nullptr};           int n3 = 0;
    const float* wH[4]  = {nullptr, nullptr, nullptr, nullptr}; int nH = 0;
    const float* bs[3]  = {nullptr, nullptr, nullptr};  int nb_ = 0;
    for (int i = 0; i < n_in; i++) {
        const int sz = in_sizes[i];
        const float* p = (const float*)d_in[i];
        if (sz == BB * NN * 3)      pts = p;
        else if (sz == HH * 3)      { if (n3 < 2) w3[n3++] = p; }
        else if (sz == HH * HH)     { if (nH < 4) wH[nH++] = p; }
        else if (sz == HH)          { if (nb_ < 3) bs[nb_++] = p; }
        // sz == 1 -> k, ignored (compile-time KNN)
    }
    const float* W1r = w3[0];  const float* W1s = w3[1];
    const float* W2r = wH[0];  const float* W2s = wH[1];
    const float* W3r = wH[2];  const float* W3s = wH[3];
    const float* b1  = bs[0];  const float* b2  = bs[1];  const float* b3 = bs[2];
    float* out = (float*)d_out;

    const int SMEM = (2 * 64 * APITCH + 2 * 16 * HH) * (int)sizeof(float);  // 83968
    cudaFuncSetAttribute(layer_kernel<true>,  cudaFuncAttributeMaxDynamicSharedMemorySize, SMEM);
    cudaFuncSetAttribute(layer_kernel<false>, cudaFuncAttributeMaxDynamicSharedMemorySize, SMEM);

    float *h1, *h2, *wt;
    cudaGetSymbolAddress((void**)&h1, g_h1);
    cudaGetSymbolAddress((void**)&h2, g_h2);
    cudaGetSymbolAddress((void**)&wt, g_WT);

    transpose_kernel<<<dim3(64, 4), 256>>>(W2r, W2s, W3r, W3s);
    knn_kernel<<<dim3(16, 16), 128>>>(pts);
    layer1_kernel<<<128, 256>>>(pts, W1r, b1, W1s);
    layer_kernel<true><<<512, 256, SMEM>>>(h1, wt, b2, wt + HH * HH, h2);
    layer_kernel<false><<<512, 256, SMEM>>>(h2, wt + 2 * HH * HH, b3, wt + 3 * HH * HH, out);
}